// round 15
// baseline (speedup 1.0000x reference)
#include <cuda_runtime.h>
#include <cuda_bf16.h>
#include <cstdint>

#define N_NODES 4096
#define D_IN    256
#define D_OUT   128
#define H_HEADS 4
#define NEG_SLOPE 0.2f
#define NWORDS  (N_NODES / 32)

typedef unsigned long long u64;

// ---------------- scratch (device globals; no allocation allowed) ----------------
__device__ float          g_h[H_HEADS * N_NODES * D_OUT];     // 8 MB fp32 h[head][j][o]
__device__ unsigned       g_mask[N_NODES * NWORDS];            // 2 MB
__device__ float          g_Ei [H_HEADS * N_NODES];
__device__ float          g_Ei2[H_HEADS * N_NODES];
__device__ float2         g_jp [H_HEADS * N_NODES];            // (exp(s_j), exp(0.2*s_j))
__device__ __nv_bfloat16  g_hbhi[H_HEADS * N_NODES * D_OUT];   // 4 MB  h hi [head][j][o]
__device__ __nv_bfloat16  g_hblo[H_HEADS * N_NODES * D_OUT];   // 4 MB  h lo

// ---------------- kernel 1: bit-pack mask = (A>0) | eye ----------------
__global__ void pack_mask_kernel(const int* __restrict__ A) {
    int g    = blockIdx.x * blockDim.x + threadIdx.x;
    int lane = g & 31;
    int word = g >> 5;
    int row  = word >> 7;
    int jw   = word & 127;
    int j    = jw * 32 + lane;
    int v = (A[row * N_NODES + j] > 0) || (j == row);
    unsigned b = __ballot_sync(0xffffffffu, v);
    if (lane == 0) g_mask[word] = b;
}

// ---------------- kernel 2: h = x @ W per head + fused hi/lo bf16 split --------
__global__ __launch_bounds__(256) void h_gemm_kernel(const float* __restrict__ x,
                                                     const float* __restrict__ W) {
    __shared__ __align__(16) float xs[32][129];
    __shared__ __align__(16) float ws[32][128];
    int head    = blockIdx.y;
    int rowbase = blockIdx.x * 128;
    int tid = threadIdx.x;
    int tx  = tid & 15;
    int ty  = tid >> 4;
    int o0  = tx * 8;

    float acc[8][8];
#pragma unroll
    for (int u = 0; u < 8; u++)
#pragma unroll
        for (int i = 0; i < 8; i++) acc[u][i] = 0.f;

    const float* Wh = W + head * D_IN * D_OUT;

    for (int k0 = 0; k0 < D_IN; k0 += 32) {
        __syncthreads();
#pragma unroll
        for (int u = 0; u < 4; u++) {
            int e4  = tid + u * 256;
            int row = e4 >> 3, kq = e4 & 7;
            float4 v = *(const float4*)&x[(rowbase + row) * D_IN + k0 + kq * 4];
            xs[kq * 4 + 0][row] = v.x;
            xs[kq * 4 + 1][row] = v.y;
            xs[kq * 4 + 2][row] = v.z;
            xs[kq * 4 + 3][row] = v.w;
        }
#pragma unroll
        for (int u = 0; u < 4; u++) {
            int e4 = tid + u * 256;
            int kk = e4 >> 5, oq = e4 & 31;
            *(float4*)&ws[kk][oq * 4] = *(const float4*)&Wh[(k0 + kk) * D_OUT + oq * 4];
        }
        __syncthreads();
#pragma unroll
        for (int kk = 0; kk < 32; kk++) {
            float wv[8];
            *(float4*)&wv[0] = *(const float4*)&ws[kk][o0];
            *(float4*)&wv[4] = *(const float4*)&ws[kk][o0 + 4];
#pragma unroll
            for (int u = 0; u < 8; u++) {
                float xv = xs[kk][ty + u * 16];
#pragma unroll
                for (int i = 0; i < 8; i++) acc[u][i] += xv * wv[i];
            }
        }
    }
#pragma unroll
    for (int u = 0; u < 8; u++) {
        int row = rowbase + ty + u * 16;
        size_t idx = (size_t)(head * N_NODES + row) * D_OUT + o0;
        float* dst = &g_h[idx];
        *(float4*)&dst[0] = make_float4(acc[u][0], acc[u][1], acc[u][2], acc[u][3]);
        *(float4*)&dst[4] = make_float4(acc[u][4], acc[u][5], acc[u][6], acc[u][7]);
        unsigned hp[4], lp[4];
#pragma unroll
        for (int i = 0; i < 4; i++) {
            float v0 = acc[u][2 * i], v1 = acc[u][2 * i + 1];
            __nv_bfloat16 h0 = __float2bfloat16(v0);
            __nv_bfloat16 h1 = __float2bfloat16(v1);
            __nv_bfloat16 l0 = __float2bfloat16(v0 - __bfloat162float(h0));
            __nv_bfloat16 l1 = __float2bfloat16(v1 - __bfloat162float(h1));
            hp[i] = (unsigned)__bfloat16_as_ushort(h0) | ((unsigned)__bfloat16_as_ushort(h1) << 16);
            lp[i] = (unsigned)__bfloat16_as_ushort(l0) | ((unsigned)__bfloat16_as_ushort(l1) << 16);
        }
        *(uint4*)&g_hbhi[idx] = make_uint4(hp[0], hp[1], hp[2], hp[3]);
        *(uint4*)&g_hblo[idx] = make_uint4(lp[0], lp[1], lp[2], lp[3]);
    }
}

// ---------------- kernel 3: s_i, s_j and separable exp factors ----------------
__global__ void sij_kernel(const float* __restrict__ a) {
    int head = blockIdx.y;
    int warp = threadIdx.x >> 5, lane = threadIdx.x & 31;
    int row  = blockIdx.x * 8 + warp;
    const float* hrow = &g_h[(head * N_NODES + row) * D_OUT];
    const float* ah   = a + head * 2 * D_OUT;
    float s1 = 0.f, s2 = 0.f;
#pragma unroll
    for (int u = 0; u < 4; u++) {
        int o = lane + u * 32;
        float hv = hrow[o];
        s1 += hv * ah[o];
        s2 += hv * ah[D_OUT + o];
    }
#pragma unroll
    for (int off = 16; off; off >>= 1) {
        s1 += __shfl_xor_sync(0xffffffffu, s1, off);
        s2 += __shfl_xor_sync(0xffffffffu, s2, off);
    }
    if (lane == 0) {
        g_Ei [head * N_NODES + row] = expf(s1);
        g_Ei2[head * N_NODES + row] = expf(NEG_SLOPE * s1);
        g_jp [head * N_NODES + row] = make_float2(expf(s2), expf(NEG_SLOPE * s2));
    }
}

// ================= mma.sync / cp.async helpers =================
#define LDSM_X4(r0, r1, r2, r3, addr) \
    asm volatile("ldmatrix.sync.aligned.m8n8.x4.shared.b16 {%0,%1,%2,%3}, [%4];" \
                 : "=r"(r0), "=r"(r1), "=r"(r2), "=r"(r3) : "r"(addr))
#define LDSM_X4T(r0, r1, r2, r3, addr) \
    asm volatile("ldmatrix.sync.aligned.m8n8.x4.trans.shared.b16 {%0,%1,%2,%3}, [%4];" \
                 : "=r"(r0), "=r"(r1), "=r"(r2), "=r"(r3) : "r"(addr))
#define MMA_BF16(d, a0, a1, a2, a3, b0, b1) \
    asm volatile("mma.sync.aligned.m16n8k16.row.col.f32.bf16.bf16.f32 " \
                 "{%0,%1,%2,%3}, {%4,%5,%6,%7}, {%8,%9}, {%0,%1,%2,%3};" \
                 : "+f"((d)[0]), "+f"((d)[1]), "+f"((d)[2]), "+f"((d)[3]) \
                 : "r"(a0), "r"(a1), "r"(a2), "r"(a3), "r"(b0), "r"(b1))
#define CP_ASYNC16(dst, src) \
    asm volatile("cp.async.cg.shared.global [%0], [%1], 16;" :: "r"(dst), "l"(src))
#define CP_COMMIT() asm volatile("cp.async.commit_group;")
#define CP_WAIT0()  asm volatile("cp.async.wait_group 0;")

__device__ __forceinline__ uint32_t smem_u32(const void* p) {
    uint32_t a;
    asm("{ .reg .u64 t; cvta.to.shared.u64 t, %1; cvt.u32.u64 %0, t; }" : "=r"(a) : "l"(p));
    return a;
}

// dynamic smem per stage: WHI 8K | WLO 8K | HHI 4K | HLO 4K = 24K; 2 stages + Z
#define SM_WHI  0
#define SM_WLO  8192
#define SM_HHI  16384
#define SM_HLO  20480
#define STG_SZ  24576
#define SM_Z    49152
#define AGG_SMEM 50176

// ---------------- kernel 4: col-split double-buffered mma.sync aggregation -----
// Grid (32, 4, 2): 128 rows x one head x one 64-col half; all 4096 j in tiles
// of 32. 256 threads (8 warps), 2 CTAs/SM (reg cap 128) so one CTA's MMA
// covers the other's W-gen/stage phase. H staged via cp.async.
// W layout: [128 i][32 j] bf16, 64B rows, chunk swz kc^((i>>1)&3).
// H layout: [32 j][64 o] bf16, 128B rows, chunk swz oc^(j&7).
__global__ __launch_bounds__(256, 2) void agg_kernel(float* __restrict__ out) {
    extern __shared__ __align__(1024) char dsm[];
    uint32_t sb = smem_u32(dsm);
    int tid  = threadIdx.x;
    int lane = tid & 31;
    int wid  = tid >> 5;
    int head = blockIdx.y;
    int halfc = blockIdx.z;
    int rowbase = blockIdx.x * 128;

    int wy = wid >> 1, wx = wid & 1;       // warp tile: 32 rows x 32 cols

    // weight-gen mapping: 2 threads per row, 16 j each (seg = j-half of 32-tile)
    int grow = tid & 127, seg = tid >> 7;
    float eiw  = g_Ei [head * N_NODES + rowbase + grow];
    float ei2w = g_Ei2[head * N_NODES + rowbase + grow];
    float Zrow = 0.f;
    const float2* jpb = &g_jp[head * N_NODES];
    const unsigned* maskrow = &g_mask[(size_t)(rowbase + grow) * NWORDS];
    int wgenbase = grow * 64;
    int wswz = (grow >> 1) & 3;

    // H cp.async mapping: 1 uint4 per thread per hi/lo buffer
    int hj  = tid >> 3;          // j 0..31
    int hoc = tid & 7;           // uint4 chunk 0..7 within 64-col half
    const char* hhiG = (const char*)(g_hbhi + (size_t)head * N_NODES * D_OUT + halfc * 64);
    const char* hloG = (const char*)(g_hblo + (size_t)head * N_NODES * D_OUT + halfc * 64);
    int hdst = hj * 128 + ((hoc ^ (hj & 7)) << 4);

    float acc[2][4][4];
#pragma unroll
    for (int m = 0; m < 2; m++)
#pragma unroll
        for (int n = 0; n < 4; n++)
#pragma unroll
            for (int e = 0; e < 4; e++) acc[m][n][e] = 0.f;

    int lt = lane >> 3, lr = lane & 7;

    auto gen_w = [&](int t, int s) {
        int jt = t * 32;
        unsigned mword = maskrow[jt >> 5];
        char* wb = dsm + s * STG_SZ;
#pragma unroll
        for (int cc = 0; cc < 2; cc++) {
            int kc = seg * 2 + cc;
            unsigned hiP[4], loP[4];
#pragma unroll
            for (int e2 = 0; e2 < 4; e2++) {
                int bit = seg * 16 + cc * 8 + e2 * 2;
                int jg  = jt + seg * 16 + cc * 8 + e2 * 2;
                float2 pa = jpb[jg];
                float2 pb = jpb[jg + 1];
                float va = fmaxf(eiw * pa.x, ei2w * pa.y);
                float vb = fmaxf(eiw * pb.x, ei2w * pb.y);
                float wa = ((mword >> bit) & 1u) ? va : 0.f;
                float wb2 = ((mword >> (bit + 1)) & 1u) ? vb : 0.f;
                Zrow += wa + wb2;
                __nv_bfloat162 h2 = __floats2bfloat162_rn(wa, wb2);
                float2 hf = __bfloat1622float2(h2);
                __nv_bfloat162 l2 = __floats2bfloat162_rn(wa - hf.x, wb2 - hf.y);
                hiP[e2] = *(unsigned*)&h2;
                loP[e2] = *(unsigned*)&l2;
            }
            int sw = wgenbase + ((kc ^ wswz) << 4);
            *(uint4*)(wb + SM_WHI + sw) = make_uint4(hiP[0], hiP[1], hiP[2], hiP[3]);
            *(uint4*)(wb + SM_WLO + sw) = make_uint4(loP[0], loP[1], loP[2], loP[3]);
        }
    };
    auto cp_h = [&](int t, int s) {
        size_t gofs = (size_t)(t * 32 + hj) * D_OUT * 2 + hoc * 16;
        uint32_t b = sb + s * STG_SZ;
        CP_ASYNC16(b + SM_HHI + hdst, hhiG + gofs);
        CP_ASYNC16(b + SM_HLO + hdst, hloG + gofs);
        CP_COMMIT();
    };

    // ---- prologue: fill stage 0 ----
    gen_w(0, 0);
    cp_h(0, 0);
    CP_WAIT0();
    __syncthreads();

    for (int t = 0; t < 128; t++) {
        int cur = t & 1, nxt = cur ^ 1;
        if (t + 1 < 128) cp_h(t + 1, nxt);       // in flight during MMA

        uint32_t bufb = sb + cur * STG_SZ;
#pragma unroll
        for (int ks = 0; ks < 2; ks++) {
            uint32_t ahi[2][4], alo[2][4];
#pragma unroll
            for (int mm = 0; mm < 2; mm++) {
                int row = wy * 32 + mm * 16 + (lt & 1) * 8 + lr;
                int kc  = ks * 2 + (lt >> 1);
                uint32_t aaddr = bufb + SM_WHI + row * 64 + ((kc ^ ((row >> 1) & 3)) << 4);
                LDSM_X4(ahi[mm][0], ahi[mm][1], ahi[mm][2], ahi[mm][3], aaddr);
                LDSM_X4(alo[mm][0], alo[mm][1], alo[mm][2], alo[mm][3], aaddr + 8192);
            }
#pragma unroll
            for (int nn = 0; nn < 2; nn++) {       // n16 groups within 32 cols
                int j  = ks * 16 + (lt & 1) * 8 + lr;
                int oc = wx * 4 + nn * 2 + (lt >> 1);
                uint32_t baddr = bufb + SM_HHI + j * 128 + ((oc ^ (j & 7)) << 4);
                uint32_t bh0, bh1, bh2, bh3, bl0, bl1, bl2, bl3;
                LDSM_X4T(bh0, bh1, bh2, bh3, baddr);
                LDSM_X4T(bl0, bl1, bl2, bl3, baddr + 4096);
#pragma unroll
                for (int mm = 0; mm < 2; mm++) {
                    MMA_BF16(acc[mm][nn * 2],     ahi[mm][0], ahi[mm][1], ahi[mm][2], ahi[mm][3], bh0, bh1);
                    MMA_BF16(acc[mm][nn * 2 + 1], ahi[mm][0], ahi[mm][1], ahi[mm][2], ahi[mm][3], bh2, bh3);
                    MMA_BF16(acc[mm][nn * 2],     ahi[mm][0], ahi[mm][1], ahi[mm][2], ahi[mm][3], bl0, bl1);
                    MMA_BF16(acc[mm][nn * 2 + 1], ahi[mm][0], ahi[mm][1], ahi[mm][2], ahi[mm][3], bl2, bl3);
                    MMA_BF16(acc[mm][nn * 2],     alo[mm][0], alo[mm][1], alo[mm][2], alo[mm][3], bh0, bh1);
                    MMA_BF16(acc[mm][nn * 2 + 1], alo[mm][0], alo[mm][1], alo[mm][2], alo[mm][3], bh2, bh3);
                }
            }
        }
        if (t + 1 < 128) gen_w(t + 1, nxt);
        CP_WAIT0();
        __syncthreads();
    }

    // ---- Z + epilogue (normalize in-kernel; Z covers full j-range) ----
    ((float*)(dsm + SM_Z))[tid] = Zrow;
    __syncthreads();
    const float* zs = (const float*)(dsm + SM_Z);

#pragma unroll
    for (int mm = 0; mm < 2; mm++) {
        int r0 = wy * 32 + mm * 16 + (lane >> 2);
        int r1 = r0 + 8;
        float iz0 = 1.f / (zs[r0] + zs[128 + r0]);
        float iz1 = 1.f / (zs[r1] + zs[128 + r1]);
        float* d0 = out + (size_t)(rowbase + r0) * (H_HEADS * D_OUT) + head * D_OUT + halfc * 64;
        float* d1 = out + (size_t)(rowbase + r1) * (H_HEADS * D_OUT) + head * D_OUT + halfc * 64;
#pragma unroll
        for (int nn = 0; nn < 2; nn++) {
#pragma unroll
            for (int b = 0; b < 2; b++) {
                int n8  = nn * 2 + b;
                int col = wx * 32 + n8 * 8 + (lane & 3) * 2;
                *(float2*)(d0 + col) = make_float2(acc[mm][n8][0] * iz0, acc[mm][n8][1] * iz0);
                *(float2*)(d1 + col) = make_float2(acc[mm][n8][2] * iz1, acc[mm][n8][3] * iz1);
            }
        }
    }
}

// ---------------- launch ----------------
extern "C" void kernel_launch(void* const* d_in, const int* in_sizes, int n_in,
                              void* d_out, int out_size) {
    const float* x = (const float*)d_in[0];
    const int*   A = (const int*)  d_in[1];
    const float* W = (const float*)d_in[2];
    const float* a = (const float*)d_in[3];
    float* out = (float*)d_out;

    cudaFuncSetAttribute(agg_kernel, cudaFuncAttributeMaxDynamicSharedMemorySize, AGG_SMEM);

    pack_mask_kernel<<<(N_NODES * N_NODES) / 256, 256>>>(A);
    h_gemm_kernel<<<dim3(N_NODES / 128, H_HEADS), 256>>>(x, W);
    sij_kernel<<<dim3(N_NODES / 8, H_HEADS), 256>>>(a);
    agg_kernel<<<dim3(N_NODES / 128, H_HEADS, 2), 256, AGG_SMEM>>>(out);
}

// round 16
// speedup vs baseline: 1.0530x; 1.0530x over previous
#include <cuda_runtime.h>
#include <cuda_bf16.h>
#include <cstdint>

#define N_NODES 4096
#define D_IN    256
#define D_OUT   128
#define H_HEADS 4
#define NEG_SLOPE 0.2f
#define NWORDS  (N_NODES / 32)

typedef unsigned long long u64;

// ---------------- scratch (device globals; no allocation allowed) ----------------
__device__ float          g_h[H_HEADS * N_NODES * D_OUT];     // 8 MB fp32 h[head][j][o]
__device__ unsigned       g_mask[N_NODES * NWORDS];            // 2 MB
__device__ float          g_Ei [H_HEADS * N_NODES];
__device__ float          g_Ei2[H_HEADS * N_NODES];
__device__ float2         g_jp [H_HEADS * N_NODES];            // (exp(s_j), exp(0.2*s_j))
__device__ __nv_bfloat16  g_hbhi[H_HEADS * N_NODES * D_OUT];   // 4 MB  h hi [head][j][o]
__device__ __nv_bfloat16  g_hblo[H_HEADS * N_NODES * D_OUT];   // 4 MB  h lo

// ---------------- kernel 1: bit-pack mask = (A>0) | eye ----------------
__global__ void pack_mask_kernel(const int* __restrict__ A) {
    int g    = blockIdx.x * blockDim.x + threadIdx.x;
    int lane = g & 31;
    int word = g >> 5;
    int row  = word >> 7;
    int jw   = word & 127;
    int j    = jw * 32 + lane;
    int v = (A[row * N_NODES + j] > 0) || (j == row);
    unsigned b = __ballot_sync(0xffffffffu, v);
    if (lane == 0) g_mask[word] = b;
}

// ---------------- kernel 2: h = x @ W per head + fused hi/lo bf16 split --------
__global__ __launch_bounds__(256) void h_gemm_kernel(const float* __restrict__ x,
                                                     const float* __restrict__ W) {
    __shared__ __align__(16) float xs[32][129];
    __shared__ __align__(16) float ws[32][128];
    int head    = blockIdx.y;
    int rowbase = blockIdx.x * 128;
    int tid = threadIdx.x;
    int tx  = tid & 15;
    int ty  = tid >> 4;
    int o0  = tx * 8;

    float acc[8][8];
#pragma unroll
    for (int u = 0; u < 8; u++)
#pragma unroll
        for (int i = 0; i < 8; i++) acc[u][i] = 0.f;

    const float* Wh = W + head * D_IN * D_OUT;

    for (int k0 = 0; k0 < D_IN; k0 += 32) {
        __syncthreads();
#pragma unroll
        for (int u = 0; u < 4; u++) {
            int e4  = tid + u * 256;
            int row = e4 >> 3, kq = e4 & 7;
            float4 v = *(const float4*)&x[(rowbase + row) * D_IN + k0 + kq * 4];
            xs[kq * 4 + 0][row] = v.x;
            xs[kq * 4 + 1][row] = v.y;
            xs[kq * 4 + 2][row] = v.z;
            xs[kq * 4 + 3][row] = v.w;
        }
#pragma unroll
        for (int u = 0; u < 4; u++) {
            int e4 = tid + u * 256;
            int kk = e4 >> 5, oq = e4 & 31;
            *(float4*)&ws[kk][oq * 4] = *(const float4*)&Wh[(k0 + kk) * D_OUT + oq * 4];
        }
        __syncthreads();
#pragma unroll
        for (int kk = 0; kk < 32; kk++) {
            float wv[8];
            *(float4*)&wv[0] = *(const float4*)&ws[kk][o0];
            *(float4*)&wv[4] = *(const float4*)&ws[kk][o0 + 4];
#pragma unroll
            for (int u = 0; u < 8; u++) {
                float xv = xs[kk][ty + u * 16];
#pragma unroll
                for (int i = 0; i < 8; i++) acc[u][i] += xv * wv[i];
            }
        }
    }
#pragma unroll
    for (int u = 0; u < 8; u++) {
        int row = rowbase + ty + u * 16;
        size_t idx = (size_t)(head * N_NODES + row) * D_OUT + o0;
        float* dst = &g_h[idx];
        *(float4*)&dst[0] = make_float4(acc[u][0], acc[u][1], acc[u][2], acc[u][3]);
        *(float4*)&dst[4] = make_float4(acc[u][4], acc[u][5], acc[u][6], acc[u][7]);
        unsigned hp[4], lp[4];
#pragma unroll
        for (int i = 0; i < 4; i++) {
            float v0 = acc[u][2 * i], v1 = acc[u][2 * i + 1];
            __nv_bfloat16 h0 = __float2bfloat16(v0);
            __nv_bfloat16 h1 = __float2bfloat16(v1);
            __nv_bfloat16 l0 = __float2bfloat16(v0 - __bfloat162float(h0));
            __nv_bfloat16 l1 = __float2bfloat16(v1 - __bfloat162float(h1));
            hp[i] = (unsigned)__bfloat16_as_ushort(h0) | ((unsigned)__bfloat16_as_ushort(h1) << 16);
            lp[i] = (unsigned)__bfloat16_as_ushort(l0) | ((unsigned)__bfloat16_as_ushort(l1) << 16);
        }
        *(uint4*)&g_hbhi[idx] = make_uint4(hp[0], hp[1], hp[2], hp[3]);
        *(uint4*)&g_hblo[idx] = make_uint4(lp[0], lp[1], lp[2], lp[3]);
    }
}

// ---------------- kernel 3: s_i, s_j and separable exp factors ----------------
__global__ void sij_kernel(const float* __restrict__ a) {
    int head = blockIdx.y;
    int warp = threadIdx.x >> 5, lane = threadIdx.x & 31;
    int row  = blockIdx.x * 8 + warp;
    const float* hrow = &g_h[(head * N_NODES + row) * D_OUT];
    const float* ah   = a + head * 2 * D_OUT;
    float s1 = 0.f, s2 = 0.f;
#pragma unroll
    for (int u = 0; u < 4; u++) {
        int o = lane + u * 32;
        float hv = hrow[o];
        s1 += hv * ah[o];
        s2 += hv * ah[D_OUT + o];
    }
#pragma unroll
    for (int off = 16; off; off >>= 1) {
        s1 += __shfl_xor_sync(0xffffffffu, s1, off);
        s2 += __shfl_xor_sync(0xffffffffu, s2, off);
    }
    if (lane == 0) {
        g_Ei [head * N_NODES + row] = expf(s1);
        g_Ei2[head * N_NODES + row] = expf(NEG_SLOPE * s1);
        g_jp [head * N_NODES + row] = make_float2(expf(s2), expf(NEG_SLOPE * s2));
    }
}

// ================= mma.sync / cp.async helpers =================
#define LDSM_X4T(r0, r1, r2, r3, addr) \
    asm volatile("ldmatrix.sync.aligned.m8n8.x4.trans.shared.b16 {%0,%1,%2,%3}, [%4];" \
                 : "=r"(r0), "=r"(r1), "=r"(r2), "=r"(r3) : "r"(addr))
#define MMA_BF16(d, a0, a1, a2, a3, b0, b1) \
    asm volatile("mma.sync.aligned.m16n8k16.row.col.f32.bf16.bf16.f32 " \
                 "{%0,%1,%2,%3}, {%4,%5,%6,%7}, {%8,%9}, {%0,%1,%2,%3};" \
                 : "+f"((d)[0]), "+f"((d)[1]), "+f"((d)[2]), "+f"((d)[3]) \
                 : "r"(a0), "r"(a1), "r"(a2), "r"(a3), "r"(b0), "r"(b1))
#define CP_ASYNC16(dst, src) \
    asm volatile("cp.async.cg.shared.global [%0], [%1], 16;" :: "r"(dst), "l"(src))
#define CP_COMMIT() asm volatile("cp.async.commit_group;")
#define CP_WAIT0()  asm volatile("cp.async.wait_group 0;")

__device__ __forceinline__ uint32_t smem_u32(const void* p) {
    uint32_t a;
    asm("{ .reg .u64 t; cvta.to.shared.u64 t, %1; cvt.u32.u64 %0, t; }" : "=r"(a) : "l"(p));
    return a;
}

// dynamic smem per stage: HHI 8K | HLO 8K = 16K; 2 stages = 32K. No W smem!
#define SM_HHI  0
#define SM_HLO  8192
#define STG_SZ  16384
#define AGG_SMEM 32768

// ---------------- kernel 4: register-direct-W mma.sync aggregation -------------
// Grid (64, 4): CTA = 64 rows x 128 cols x one head, all 4096 j in tiles of 32.
// 256 threads (8 warps): wy = wid>>1 -> 16-row m-tile (rows wy*16..+15),
// wx = wid&1 -> 64-col half. 2 CTAs/SM.
// W NEVER touches smem: each lane generates its A-fragment weights directly
// (m16n8k16 A map: rows lane>>2, +8; j (lane&3)*2 +{0,1,8,9}), Z reduced by
// shfl over the 4 lanes sharing a row. Only H is staged (cp.async, dbl-buf).
__global__ __launch_bounds__(256, 2) void agg_kernel(float* __restrict__ out) {
    extern __shared__ __align__(1024) char dsm[];
    uint32_t sb = smem_u32(dsm);
    int tid  = threadIdx.x;
    int lane = tid & 31;
    int wid  = tid >> 5;
    int head = blockIdx.y;
    int rowbase = blockIdx.x * 64;

    int wy = wid >> 1, wx = wid & 1;
    int lt = lane >> 3, lr = lane & 7;

    // this lane's two A-fragment rows
    int r0g = rowbase + wy * 16 + (lane >> 2);
    int r1g = r0g + 8;
    float eiw0  = g_Ei [head * N_NODES + r0g], ei2w0 = g_Ei2[head * N_NODES + r0g];
    float eiw1  = g_Ei [head * N_NODES + r1g], ei2w1 = g_Ei2[head * N_NODES + r1g];
    const unsigned* mrow0 = &g_mask[(size_t)r0g * NWORDS];
    const unsigned* mrow1 = &g_mask[(size_t)r1g * NWORDS];
    const float4* jp4 = (const float4*)(g_jp + head * N_NODES);
    float Z0 = 0.f, Z1 = 0.f;

    // H cp.async mapping: 512 uint4 per buffer (32 j x 16 chunks), 2/thread
    const char* hhiG = (const char*)(g_hbhi + (size_t)head * N_NODES * D_OUT);
    const char* hloG = (const char*)(g_hblo + (size_t)head * N_NODES * D_OUT);

    float acc[8][4];
#pragma unroll
    for (int n = 0; n < 8; n++)
#pragma unroll
        for (int e = 0; e < 4; e++) acc[n][e] = 0.f;

    auto cp_h = [&](int t, int s) {
        uint32_t b = sb + s * STG_SZ;
#pragma unroll
        for (int r = 0; r < 2; r++) {
            int id = tid + r * 256;          // 0..511
            int j  = id >> 4, oc = id & 15;
            size_t gofs = (size_t)(t * 32 + j) * 256 + oc * 16;
            int ad = j * 256 + ((oc ^ (j & 7)) << 4);
            CP_ASYNC16(b + SM_HHI + ad, hhiG + gofs);
            CP_ASYNC16(b + SM_HLO + ad, hloG + gofs);
        }
        CP_COMMIT();
    };

    // ---- prologue ----
    cp_h(0, 0);
    CP_WAIT0();
    __syncthreads();

    for (int t = 0; t < 128; t++) {
        int cur = t & 1, nxt = cur ^ 1;
        if (t + 1 < 128) cp_h(t + 1, nxt);

        int jt = t * 32;
        unsigned mw0 = mrow0[jt >> 5];
        unsigned mw1 = mrow1[jt >> 5];
        uint32_t bufb = sb + cur * STG_SZ;

#pragma unroll
        for (int ks = 0; ks < 2; ks++) {
            // ---- generate A fragments in registers (hi + lo) ----
            int jb   = jt + ks * 16 + (lane & 3) * 2;   // even
            int bit0 = ks * 16 + (lane & 3) * 2;
            float4 q0 = jp4[jb >> 1];           // jp[jb], jp[jb+1]
            float4 q1 = jp4[(jb >> 1) + 4];     // jp[jb+8], jp[jb+9]

            uint32_t ahi[4], alo[4];
            // a0: row r0, j jb/jb+1 ; a1: row r1 same j ; a2: r0, jb+8/9 ; a3: r1, jb+8/9
            {
                float w00 = ((mw0 >> bit0) & 1u)       ? fmaxf(eiw0 * q0.x, ei2w0 * q0.y) : 0.f;
                float w01 = ((mw0 >> (bit0 + 1)) & 1u) ? fmaxf(eiw0 * q0.z, ei2w0 * q0.w) : 0.f;
                float w10 = ((mw1 >> bit0) & 1u)       ? fmaxf(eiw1 * q0.x, ei2w1 * q0.y) : 0.f;
                float w11 = ((mw1 >> (bit0 + 1)) & 1u) ? fmaxf(eiw1 * q0.z, ei2w1 * q0.w) : 0.f;
                float w02 = ((mw0 >> (bit0 + 8)) & 1u) ? fmaxf(eiw0 * q1.x, ei2w0 * q1.y) : 0.f;
                float w03 = ((mw0 >> (bit0 + 9)) & 1u) ? fmaxf(eiw0 * q1.z, ei2w0 * q1.w) : 0.f;
                float w12 = ((mw1 >> (bit0 + 8)) & 1u) ? fmaxf(eiw1 * q1.x, ei2w1 * q1.y) : 0.f;
                float w13 = ((mw1 >> (bit0 + 9)) & 1u) ? fmaxf(eiw1 * q1.z, ei2w1 * q1.w) : 0.f;
                Z0 += w00 + w01 + w02 + w03;
                Z1 += w10 + w11 + w12 + w13;
                __nv_bfloat162 h;
                float2 hf;
                h = __floats2bfloat162_rn(w00, w01); hf = __bfloat1622float2(h);
                ahi[0] = *(uint32_t*)&h;
                { __nv_bfloat162 l = __floats2bfloat162_rn(w00 - hf.x, w01 - hf.y); alo[0] = *(uint32_t*)&l; }
                h = __floats2bfloat162_rn(w10, w11); hf = __bfloat1622float2(h);
                ahi[1] = *(uint32_t*)&h;
                { __nv_bfloat162 l = __floats2bfloat162_rn(w10 - hf.x, w11 - hf.y); alo[1] = *(uint32_t*)&l; }
                h = __floats2bfloat162_rn(w02, w03); hf = __bfloat1622float2(h);
                ahi[2] = *(uint32_t*)&h;
                { __nv_bfloat162 l = __floats2bfloat162_rn(w02 - hf.x, w03 - hf.y); alo[2] = *(uint32_t*)&l; }
                h = __floats2bfloat162_rn(w12, w13); hf = __bfloat1622float2(h);
                ahi[3] = *(uint32_t*)&h;
                { __nv_bfloat162 l = __floats2bfloat162_rn(w12 - hf.x, w13 - hf.y); alo[3] = *(uint32_t*)&l; }
            }

            // ---- B fragments + 3-term MMAs over 8 n8-groups (64 cols) ----
#pragma unroll
            for (int nn = 0; nn < 4; nn++) {
                int j  = ks * 16 + (lt & 1) * 8 + lr;
                int oc = wx * 8 + nn * 2 + (lt >> 1);
                uint32_t baddr = bufb + SM_HHI + j * 256 + ((oc ^ (j & 7)) << 4);
                uint32_t bh0, bh1, bh2, bh3, bl0, bl1, bl2, bl3;
                LDSM_X4T(bh0, bh1, bh2, bh3, baddr);
                LDSM_X4T(bl0, bl1, bl2, bl3, baddr + 8192);
                MMA_BF16(acc[nn * 2],     ahi[0], ahi[1], ahi[2], ahi[3], bh0, bh1);
                MMA_BF16(acc[nn * 2 + 1], ahi[0], ahi[1], ahi[2], ahi[3], bh2, bh3);
                MMA_BF16(acc[nn * 2],     ahi[0], ahi[1], ahi[2], ahi[3], bl0, bl1);
                MMA_BF16(acc[nn * 2 + 1], ahi[0], ahi[1], ahi[2], ahi[3], bl2, bl3);
                MMA_BF16(acc[nn * 2],     alo[0], alo[1], alo[2], alo[3], bh0, bh1);
                MMA_BF16(acc[nn * 2 + 1], alo[0], alo[1], alo[2], alo[3], bh2, bh3);
            }
        }
        CP_WAIT0();
        __syncthreads();
    }

    // ---- Z reduce (over the 4 lanes sharing each row) + epilogue ----
    Z0 += __shfl_xor_sync(0xffffffffu, Z0, 1);
    Z0 += __shfl_xor_sync(0xffffffffu, Z0, 2);
    Z1 += __shfl_xor_sync(0xffffffffu, Z1, 1);
    Z1 += __shfl_xor_sync(0xffffffffu, Z1, 2);
    float iz0 = 1.f / Z0, iz1 = 1.f / Z1;

    float* d0 = out + (size_t)r0g * (H_HEADS * D_OUT) + head * D_OUT;
    float* d1 = out + (size_t)r1g * (H_HEADS * D_OUT) + head * D_OUT;
#pragma unroll
    for (int n8 = 0; n8 < 8; n8++) {
        int col = wx * 64 + n8 * 8 + (lane & 3) * 2;
        *(float2*)(d0 + col) = make_float2(acc[n8][0] * iz0, acc[n8][1] * iz0);
        *(float2*)(d1 + col) = make_float2(acc[n8][2] * iz1, acc[n8][3] * iz1);
    }
}

// ---------------- launch ----------------
extern "C" void kernel_launch(void* const* d_in, const int* in_sizes, int n_in,
                              void* d_out, int out_size) {
    const float* x = (const float*)d_in[0];
    const int*   A = (const int*)  d_in[1];
    const float* W = (const float*)d_in[2];
    const float* a = (const float*)d_in[3];
    float* out = (float*)d_out;

    cudaFuncSetAttribute(agg_kernel, cudaFuncAttributeMaxDynamicSharedMemorySize, AGG_SMEM);

    pack_mask_kernel<<<(N_NODES * N_NODES) / 256, 256>>>(A);
    h_gemm_kernel<<<dim3(N_NODES / 128, H_HEADS), 256>>>(x, W);
    sij_kernel<<<dim3(N_NODES / 8, H_HEADS), 256>>>(a);
    agg_kernel<<<dim3(N_NODES / 64, H_HEADS), 256, AGG_SMEM>>>(out);
}